// round 7
// baseline (speedup 1.0000x reference)
#include <cuda_runtime.h>
#include <cuda_fp16.h>
#include <math.h>
#include <cstdint>

// Problem dims (fixed)
#define NB 32
#define NT 1024
#define NC 512
#define NL 252
#define NP 256
#define NS 128
#define NBT (NB*NT)

// fp32 scratch
static __device__ float g_q[NBT*NC];
static __device__ float g_query[NBT*NC];
static __device__ float g_tmp[NBT*NC];
// fp16 scratch
static __device__ __half g_xh[NBT*NC];
static __device__ __half g_qh[NBT*NC];
static __device__ __half g_queryh[NBT*NC];
static __device__ __half g_hh[NBT*2*NC];
static __device__ __half g_kh[NB*NS*NC];
static __device__ __half g_vTh[NB*NC*NS];
static __device__ __half g_wqh[NC*NC];
static __device__ __half g_w1h[2*NC*NC];
static __device__ __half g_w2h[NC*2*NC];

// ---------------------------------------------------------------------------
__device__ __forceinline__ uint32_t smem_u32(const void* p) {
    uint32_t a;
    asm("{ .reg .u64 t; cvta.to.shared.u64 t, %1; cvt.u32.u64 %0, t; }" : "=r"(a) : "l"(p));
    return a;
}
__device__ __forceinline__ void cp16(uint32_t dst, const void* src) {
    asm volatile("cp.async.cg.shared.global [%0], [%1], 16;" :: "r"(dst), "l"(src) : "memory");
}
template<int N> __device__ __forceinline__ void cp_wait() {
    asm volatile("cp.async.wait_group %0;" :: "n"(N) : "memory");
}
__device__ __forceinline__ void cp_commit() { asm volatile("cp.async.commit_group;" ::: "memory"); }

// m16n8k16 fp16 MMA, fp32 accumulate
__device__ __forceinline__ void mma16(float* c, const uint32_t* a, uint32_t b0, uint32_t b1) {
    asm volatile(
        "mma.sync.aligned.m16n8k16.row.col.f32.f16.f16.f32 "
        "{%0,%1,%2,%3}, {%4,%5,%6,%7}, {%8,%9}, {%0,%1,%2,%3};"
        : "+f"(c[0]), "+f"(c[1]), "+f"(c[2]), "+f"(c[3])
        : "r"(a[0]), "r"(a[1]), "r"(a[2]), "r"(a[3]), "r"(b0), "r"(b1));
}

// ldmatrix x4: loads four 8x8 b16 matrices
__device__ __forceinline__ void ldsm4(uint32_t* r, uint32_t addr) {
    asm volatile("ldmatrix.sync.aligned.m8n8.x4.shared.b16 {%0,%1,%2,%3}, [%4];"
                 : "=r"(r[0]), "=r"(r[1]), "=r"(r[2]), "=r"(r[3]) : "r"(addr));
}

// ---------------------------------------------------------------------------
// fp16 HMMA GEMM with ldmatrix fragment loads.
// A: [M,K] K-major half, B: [N,K] K-major half. CTA 128x128, BK=32, 256 thr.
// Warp grid 2(m) x 4(n), warp tile 64x32. Smem rows 80 bytes (stride 20 words).
// ---------------------------------------------------------------------------
#define SROWW 20
#define STG_WORDS (128*SROWW)
#define GEMM_SMEM (2*2*STG_WORDS*4)

template<int EPI>
__global__ void __launch_bounds__(256)
gemm_h(const __half* __restrict__ A, const __half* __restrict__ B,
       const float* __restrict__ bias, float* __restrict__ C, __half* __restrict__ Ch,
       int K, int ldc, float scale,
       long long sA, long long sB, long long sC)
{
    extern __shared__ uint32_t smw[];
    const uint32_t sbase = smem_u32(smw);
    const int tid = threadIdx.x;
    const int wid = tid >> 5, lane = tid & 31;
    const int g = lane >> 2, tig = lane & 3;
    const int wm = wid & 1, wn = wid >> 1;
    const int m0 = blockIdx.y * 128, n0 = blockIdx.x * 128;
    A += blockIdx.z * sA + (long long)m0 * K;
    B += blockIdx.z * sB + (long long)n0 * K;
    if (C)  C  += blockIdx.z * sC;
    if (Ch) Ch += blockIdx.z * sC;
    const int nk = K >> 5;
    const uint32_t lpart = (lane & 15) * 80 + ((lane >> 4) * 16);

    float acc[4][4][4];
#pragma unroll
    for (int i = 0; i < 4; i++)
#pragma unroll
        for (int j = 0; j < 4; j++)
#pragma unroll
            for (int q = 0; q < 4; q++) acc[i][j][q] = 0.f;

    auto stage = [&](int chunk, int stg) {
        uint32_t ab = sbase + stg * (2 * STG_WORDS * 4);
        uint32_t bb = ab + STG_WORDS * 4;
        const __half* Ac = A + chunk * 32;
        const __half* Bc = B + chunk * 32;
#pragma unroll
        for (int i = 0; i < 2; i++) {
            int idx = i * 256 + tid;
            int row = idx >> 2, c8 = idx & 3;
            uint32_t so = row * 80 + c8 * 16;
            cp16(ab + so, Ac + (long long)row * K + c8 * 8);
            cp16(bb + so, Bc + (long long)row * K + c8 * 8);
        }
        cp_commit();
    };

    stage(0, 0);
    for (int kc = 0; kc < nk; kc++) {
        if (kc + 1 < nk) { stage(kc + 1, (kc + 1) & 1); cp_wait<1>(); }
        else            { cp_wait<0>(); }
        __syncthreads();
        const uint32_t base = sbase + (kc & 1) * (2 * STG_WORDS * 4);
        const uint32_t Abase = base + (wm * 64) * 80 + lpart;
        const uint32_t Bbase = base + STG_WORDS * 4 + (wn * 32) * 80 + lpart;
#pragma unroll
        for (int slab = 0; slab < 2; slab++) {
            uint32_t af[4][4], bf[2][4];
#pragma unroll
            for (int mt = 0; mt < 4; mt++)
                ldsm4(af[mt], Abase + mt * (16 * 80) + slab * 32);
#pragma unroll
            for (int np = 0; np < 2; np++)
                ldsm4(bf[np], Bbase + np * (16 * 80) + slab * 32);
#pragma unroll
            for (int mt = 0; mt < 4; mt++)
#pragma unroll
                for (int np = 0; np < 2; np++) {
                    mma16(acc[mt][np * 2 + 0], af[mt], bf[np][0], bf[np][2]);
                    mma16(acc[mt][np * 2 + 1], af[mt], bf[np][1], bf[np][3]);
                }
        }
        __syncthreads();
    }

#pragma unroll
    for (int mt = 0; mt < 4; mt++) {
#pragma unroll
        for (int hf = 0; hf < 2; hf++) {
            int row = m0 + wm * 64 + mt * 16 + g + hf * 8;
#pragma unroll
            for (int nt = 0; nt < 4; nt++) {
                int col = n0 + wn * 32 + nt * 8 + 2 * tig;
                float v0 = acc[mt][nt][hf * 2 + 0] * scale;
                float v1 = acc[mt][nt][hf * 2 + 1] * scale;
                if (bias) { v0 += bias[col]; v1 += bias[col + 1]; }
                if (EPI == 1) {
                    v0 = 0.5f * v0 * (1.0f + erff(v0 * 0.70710678118654752f));
                    v1 = 0.5f * v1 * (1.0f + erff(v1 * 0.70710678118654752f));
                }
                if (C) {
                    float2 o; o.x = v0; o.y = v1;
                    *(float2*)(C + (long long)row * ldc + col) = o;
                }
                if (Ch)
                    *(__half2*)(Ch + (long long)row * ldc + col) = __floats2half2_rn(v0, v1);
            }
        }
    }
}

// ---------------------------------------------------------------------------
// Fused attention: scores = qh@kh^T, softmax, P@V, +q residual, LN1.
// Smem layout unchanged from round 6; fragment loads now via ldmatrix.
// ---------------------------------------------------------------------------
#define ATT_SMEM 93184
#define PROWW 68

__global__ void __launch_bounds__(256)
attn_fused(const __half* __restrict__ qhp, const __half* __restrict__ khp,
           const __half* __restrict__ vTp, const float* __restrict__ qf,
           const float* __restrict__ lnw, const float* __restrict__ lnb,
           float* __restrict__ uout, float* __restrict__ query,
           __half* __restrict__ queryh)
{
    extern __shared__ uint32_t smw[];
    const uint32_t sbase = smem_u32(smw);
    const int tid = threadIdx.x;
    const int wid = tid >> 5, lane = tid & 31;
    const int g = lane >> 2, tig = lane & 3;
    const int wm = wid & 1, wn = wid >> 1;
    const int m0 = blockIdx.x * 128;
    const int b = blockIdx.y;
    const __half* A = qhp + ((long long)b * NT + m0) * NC;
    const __half* B = khp + (long long)b * NS * NC;
    const __half* V = vTp + (long long)b * NC * NS;
    const int slot = wn * 4 + tig;
    const uint32_t lp80  = (lane & 15) * 80  + ((lane >> 4) * 16);
    const uint32_t lp272 = (lane & 15) * 272 + ((lane >> 4) * 16);

    float* RED = (float*)(smw + 18944);
    float* RSQ = RED + 2048;
    float2* RST = (float2*)(smw + 23040);

    float acc[4][4][4];
#pragma unroll
    for (int i = 0; i < 4; i++)
#pragma unroll
        for (int j = 0; j < 4; j++)
#pragma unroll
            for (int q = 0; q < 4; q++) acc[i][j][q] = 0.f;

    // ---- Phase 1: scores = Q K^T ----
    auto stage = [&](int chunk, int stg) {
        uint32_t ab = sbase + stg * (2 * STG_WORDS * 4);
        uint32_t bb = ab + STG_WORDS * 4;
        const __half* Ac = A + chunk * 32;
        const __half* Bc = B + chunk * 32;
#pragma unroll
        for (int i = 0; i < 2; i++) {
            int idx = i * 256 + tid;
            int row = idx >> 2, c8 = idx & 3;
            uint32_t so = row * 80 + c8 * 16;
            cp16(ab + so, Ac + (long long)row * NC + c8 * 8);
            cp16(bb + so, Bc + (long long)row * NC + c8 * 8);
        }
        cp_commit();
    };

    stage(0, 0);
    for (int kc = 0; kc < 16; kc++) {
        if (kc + 1 < 16) { stage(kc + 1, (kc + 1) & 1); cp_wait<1>(); }
        else            { cp_wait<0>(); }
        __syncthreads();
        const uint32_t base = sbase + (kc & 1) * (2 * STG_WORDS * 4);
        const uint32_t Abase = base + (wm * 64) * 80 + lp80;
        const uint32_t Bbase = base + STG_WORDS * 4 + (wn * 32) * 80 + lp80;
#pragma unroll
        for (int slab = 0; slab < 2; slab++) {
            uint32_t af[4][4], bf[2][4];
#pragma unroll
            for (int mt = 0; mt < 4; mt++)
                ldsm4(af[mt], Abase + mt * (16 * 80) + slab * 32);
#pragma unroll
            for (int np = 0; np < 2; np++)
                ldsm4(bf[np], Bbase + np * (16 * 80) + slab * 32);
#pragma unroll
            for (int mt = 0; mt < 4; mt++)
#pragma unroll
                for (int np = 0; np < 2; np++) {
                    mma16(acc[mt][np * 2 + 0], af[mt], bf[np][0], bf[np][2]);
                    mma16(acc[mt][np * 2 + 1], af[mt], bf[np][1], bf[np][3]);
                }
        }
        __syncthreads();
    }

    // ---- Phase 2: softmax over 128 cols per row ----
    const float scl = 0.04419417382415922f;  // 1/sqrt(512)
#pragma unroll
    for (int idx = 0; idx < 8; idx++) {
        int mt = idx >> 1, hf = idx & 1;
        float m = -1e30f;
#pragma unroll
        for (int nt = 0; nt < 4; nt++) {
            m = fmaxf(m, acc[mt][nt][hf * 2 + 0]);
            m = fmaxf(m, acc[mt][nt][hf * 2 + 1]);
        }
        int r = wm * 64 + mt * 16 + g + hf * 8;
        RED[r * 16 + slot] = m;
    }
    __syncthreads();
    if (tid < 128) {
        float m = -1e30f;
#pragma unroll
        for (int k = 0; k < 16; k++) m = fmaxf(m, RED[tid * 16 + k]);
        RST[tid].x = m;
    }
    __syncthreads();
#pragma unroll
    for (int idx = 0; idx < 8; idx++) {
        int mt = idx >> 1, hf = idx & 1;
        int r = wm * 64 + mt * 16 + g + hf * 8;
        float rmax = RST[r].x;
        float s = 0.f;
#pragma unroll
        for (int nt = 0; nt < 4; nt++) {
            float p0 = expf(scl * (acc[mt][nt][hf * 2 + 0] - rmax));
            float p1 = expf(scl * (acc[mt][nt][hf * 2 + 1] - rmax));
            acc[mt][nt][hf * 2 + 0] = p0;
            acc[mt][nt][hf * 2 + 1] = p1;
            s += p0 + p1;
        }
        RED[r * 16 + slot] = s;
    }
    __syncthreads();
    if (tid < 128) {
        float s = 0.f;
#pragma unroll
        for (int k = 0; k < 16; k++) s += RED[tid * 16 + k];
        RST[tid].y = 1.0f / s;
    }
    __syncthreads();
#pragma unroll
    for (int idx = 0; idx < 8; idx++) {
        int mt = idx >> 1, hf = idx & 1;
        int r = wm * 64 + mt * 16 + g + hf * 8;
        float inv = RST[r].y;
#pragma unroll
        for (int nt = 0; nt < 4; nt++) {
            __half2 h = __floats2half2_rn(acc[mt][nt][hf * 2 + 0] * inv,
                                          acc[mt][nt][hf * 2 + 1] * inv);
            smw[10240 + r * PROWW + wn * 16 + nt * 4 + tig] = *(uint32_t*)&h;
        }
    }
    __syncthreads();

    // ---- Phase 3: out = P @ V, + q residual, LN1 stats ----
    float psum[8], psq[8];
#pragma unroll
    for (int i = 0; i < 8; i++) { psum[i] = 0.f; psq[i] = 0.f; }
    const uint32_t Pbase = sbase + 40960 + (wm * 64) * 272 + lp272;

    for (int chunk = 0; chunk < 4; chunk++) {
#pragma unroll
        for (int i = 0; i < 8; i++) {
            int idx = i * 256 + tid;
            int row = idx >> 4, c16 = idx & 15;
            cp16(sbase + row * 272 + c16 * 16,
                 V + (long long)(chunk * 128 + row) * NS + c16 * 8);
        }
        cp_commit(); cp_wait<0>();
        __syncthreads();

        float a2[4][4][4];
#pragma unroll
        for (int i = 0; i < 4; i++)
#pragma unroll
            for (int j = 0; j < 4; j++)
#pragma unroll
                for (int q = 0; q < 4; q++) a2[i][j][q] = 0.f;

        const uint32_t Vbase = sbase + (wn * 32) * 272 + lp272;
#pragma unroll
        for (int slab = 0; slab < 8; slab++) {
            uint32_t af[4][4], bf[2][4];
#pragma unroll
            for (int mt = 0; mt < 4; mt++)
                ldsm4(af[mt], Pbase + mt * (16 * 272) + slab * 32);
#pragma unroll
            for (int np = 0; np < 2; np++)
                ldsm4(bf[np], Vbase + np * (16 * 272) + slab * 32);
#pragma unroll
            for (int mt = 0; mt < 4; mt++)
#pragma unroll
                for (int np = 0; np < 2; np++) {
                    mma16(a2[mt][np * 2 + 0], af[mt], bf[np][0], bf[np][2]);
                    mma16(a2[mt][np * 2 + 1], af[mt], bf[np][1], bf[np][3]);
                }
        }

#pragma unroll
        for (int idx = 0; idx < 8; idx++) {
            int mt = idx >> 1, hf = idx & 1;
            long long grow = (long long)b * NT + m0 + wm * 64 + mt * 16 + g + hf * 8;
#pragma unroll
            for (int nt = 0; nt < 4; nt++) {
                int col = chunk * 128 + wn * 32 + nt * 8 + 2 * tig;
                float2 qv = *(const float2*)(qf + grow * NC + col);
                float u0 = a2[mt][nt][hf * 2 + 0] + qv.x;
                float u1 = a2[mt][nt][hf * 2 + 1] + qv.y;
                psum[idx] += u0 + u1;
                psq[idx]  += u0 * u0 + u1 * u1;
                float2 o; o.x = u0; o.y = u1;
                *(float2*)(uout + grow * NC + col) = o;
            }
        }
        __syncthreads();
    }

    // ---- LN1 reduce + normalize ----
#pragma unroll
    for (int idx = 0; idx < 8; idx++) {
        int mt = idx >> 1, hf = idx & 1;
        int r = wm * 64 + mt * 16 + g + hf * 8;
        RED[r * 16 + slot] = psum[idx];
        RSQ[r * 16 + slot] = psq[idx];
    }
    __syncthreads();
    if (tid < 128) {
        float s = 0.f, sq = 0.f;
#pragma unroll
        for (int k = 0; k < 16; k++) { s += RED[tid * 16 + k]; sq += RSQ[tid * 16 + k]; }
        float mu = s * (1.0f / NC);
        float var = sq * (1.0f / NC) - mu * mu;
        RST[tid].x = mu;
        RST[tid].y = rsqrtf(var + 1e-5f);
    }
    __syncthreads();
#pragma unroll
    for (int idx = 0; idx < 8; idx++) {
        int mt = idx >> 1, hf = idx & 1;
        int r = wm * 64 + mt * 16 + g + hf * 8;
        float2 st = RST[r];
        long long grow = (long long)b * NT + m0 + r;
#pragma unroll
        for (int chunk = 0; chunk < 4; chunk++) {
#pragma unroll
            for (int nt = 0; nt < 4; nt++) {
                int col = chunk * 128 + wn * 32 + nt * 8 + 2 * tig;
                float2 u = *(const float2*)(uout + grow * NC + col);
                float o0 = (u.x - st.x) * st.y * lnw[col]     + lnb[col];
                float o1 = (u.y - st.x) * st.y * lnw[col + 1] + lnb[col + 1];
                float2 o; o.x = o0; o.y = o1;
                *(float2*)(query + grow * NC + col) = o;
                *(__half2*)(queryh + grow * NC + col) = __floats2half2_rn(o0, o1);
            }
        }
    }
}

// ---------------------------------------------------------------------------
// K/V via rank-1 conditioner; writes kh[b][s][c] and vTh[b][c][s] (fp16)
// ---------------------------------------------------------------------------
__global__ void cond_kv_kernel(const float* __restrict__ cond_emb,
                               const float* __restrict__ Wk, const float* __restrict__ bk,
                               const float* __restrict__ Wv, const float* __restrict__ bv,
                               const float* __restrict__ conv_w, const float* __restrict__ conv_b)
{
    int b = blockIdx.y;
    int c = blockIdx.x * blockDim.x + threadIdx.x;
    __shared__ float pad[NP];
    const float* ce = cond_emb + (long long)b * NL;
    for (int j = threadIdx.x; j < NP; j += blockDim.x)
        pad[j] = ce[(j + NL - 2) % NL];
    __syncthreads();

    float pk = 0.f, pv = 0.f, wks = 0.f, wvs = 0.f;
    const float* wkr = Wk + (long long)c * NP;
    const float* wvr = Wv + (long long)c * NP;
#pragma unroll 4
    for (int j = 0; j < NP; j++) {
        float p = pad[j];
        float a = wkr[j], bb = wvr[j];
        pk += p * a;  wks += a;
        pv += p * bb; wvs += bb;
    }
    float bkc = bk[c], bvc = bv[c];
    for (int s = 0; s < NS; s++) {
        float cw = conv_w[s], cb = conv_b[s];
        g_kh[((long long)b * NS + s) * NC + c]  = __float2half_rn(cw * pk + cb * wks + bkc);
        g_vTh[((long long)b * NC + c) * NS + s] = __float2half_rn(cw * pv + cb * wvs + bvc);
    }
}

// ---------------------------------------------------------------------------
__global__ void cvt_all_kernel(const float* __restrict__ x,  __half* __restrict__ xh,
                               const float* __restrict__ Wq, __half* __restrict__ wqh,
                               const float* __restrict__ W1, __half* __restrict__ w1h,
                               const float* __restrict__ W2, __half* __restrict__ w2h)
{
    const int n0 = NBT*NC/4, n1 = n0 + NC*NC/4, n2 = n1 + 2*NC*NC/4, n3 = n2 + 2*NC*NC/4;
    int i = blockIdx.x * blockDim.x + threadIdx.x;
    const float* s; __half* d; int off;
    if      (i < n0) { s = x;  d = xh;  off = i; }
    else if (i < n1) { s = Wq; d = wqh; off = i - n0; }
    else if (i < n2) { s = W1; d = w1h; off = i - n1; }
    else if (i < n3) { s = W2; d = w2h; off = i - n2; }
    else return;
    float4 v = ((const float4*)s)[off];
    ((__half2*)d)[2*off]   = __floats2half2_rn(v.x, v.y);
    ((__half2*)d)[2*off+1] = __floats2half2_rn(v.z, v.w);
}

// ---------------------------------------------------------------------------
__global__ void ln_kernel(const float* __restrict__ a, const float* __restrict__ b,
                          const float* __restrict__ w, const float* __restrict__ bb,
                          const float* __restrict__ addx, float* __restrict__ out)
{
    long long row = blockIdx.x;
    int t = threadIdx.x;
    float4 av = ((const float4*)(a + row * NC))[t];
    float4 bv = ((const float4*)(b + row * NC))[t];
    float4 u; u.x = av.x + bv.x; u.y = av.y + bv.y; u.z = av.z + bv.z; u.w = av.w + bv.w;
    float s  = u.x + u.y + u.z + u.w;
    float sq = u.x*u.x + u.y*u.y + u.z*u.z + u.w*u.w;
#pragma unroll
    for (int o = 16; o; o >>= 1) {
        s  += __shfl_xor_sync(0xffffffffu, s,  o);
        sq += __shfl_xor_sync(0xffffffffu, sq, o);
    }
    __shared__ float ss[4], sqs[4];
    int wid = t >> 5, lane = t & 31;
    if (lane == 0) { ss[wid] = s; sqs[wid] = sq; }
    __syncthreads();
    s  = ss[0] + ss[1] + ss[2] + ss[3];
    sq = sqs[0] + sqs[1] + sqs[2] + sqs[3];
    float mu  = s * (1.0f / NC);
    float var = sq * (1.0f / NC) - mu * mu;
    float inv = rsqrtf(var + 1e-5f);
    float4 wv  = ((const float4*)w)[t];
    float4 bv2 = ((const float4*)bb)[t];
    float4 o;
    o.x = (u.x - mu) * inv * wv.x + bv2.x;
    o.y = (u.y - mu) * inv * wv.y + bv2.y;
    o.z = (u.z - mu) * inv * wv.z + bv2.z;
    o.w = (u.w - mu) * inv * wv.w + bv2.w;
    float4 xv = ((const float4*)(addx + row * NC))[t];
    o.x += xv.x; o.y += xv.y; o.z += xv.z; o.w += xv.w;
    ((float4*)(out + row * NC))[t] = o;
}

// ---------------------------------------------------------------------------
extern "C" void kernel_launch(void* const* d_in, const int* in_sizes, int n_in,
                              void* d_out, int out_size)
{
    const float* x     = (const float*)d_in[0];
    const float* ce    = (const float*)d_in[1];
    const float* Wq    = (const float*)d_in[2];
    const float* bq    = (const float*)d_in[3];
    const float* Wk    = (const float*)d_in[4];
    const float* bk    = (const float*)d_in[5];
    const float* Wv    = (const float*)d_in[6];
    const float* bv    = (const float*)d_in[7];
    const float* convw = (const float*)d_in[8];
    const float* convb = (const float*)d_in[9];
    const float* ln1w  = (const float*)d_in[10];
    const float* ln1b  = (const float*)d_in[11];
    const float* W1    = (const float*)d_in[12];
    const float* b1    = (const float*)d_in[13];
    const float* W2    = (const float*)d_in[14];
    const float* b2    = (const float*)d_in[15];
    const float* ln2w  = (const float*)d_in[16];
    const float* ln2b  = (const float*)d_in[17];
    float* out = (float*)d_out;

    float *q, *query, *tmp;
    __half *xh, *qh, *queryh, *hh, *kh, *vTh, *wqh, *w1h, *w2h;
    cudaGetSymbolAddress((void**)&q,      g_q);
    cudaGetSymbolAddress((void**)&query,  g_query);
    cudaGetSymbolAddress((void**)&tmp,    g_tmp);
    cudaGetSymbolAddress((void**)&xh,     g_xh);
    cudaGetSymbolAddress((void**)&qh,     g_qh);
    cudaGetSymbolAddress((void**)&queryh, g_queryh);
    cudaGetSymbolAddress((void**)&hh,     g_hh);
    cudaGetSymbolAddress((void**)&kh,     g_kh);
    cudaGetSymbolAddress((void**)&vTh,    g_vTh);
    cudaGetSymbolAddress((void**)&wqh,    g_wqh);
    cudaGetSymbolAddress((void**)&w1h,    g_w1h);
    cudaGetSymbolAddress((void**)&w2h,    g_w2h);

    cudaFuncSetAttribute(gemm_h<0>, cudaFuncAttributeMaxDynamicSharedMemorySize, GEMM_SMEM);
    cudaFuncSetAttribute(gemm_h<1>, cudaFuncAttributeMaxDynamicSharedMemorySize, GEMM_SMEM);
    cudaFuncSetAttribute(attn_fused, cudaFuncAttributeMaxDynamicSharedMemorySize, ATT_SMEM);

    // 0) fp16 conversions (merged)
    {
        int n3 = NBT*NC/4 + NC*NC/4 + 2*NC*NC/4 + 2*NC*NC/4;
        cvt_all_kernel<<<(n3 + 255)/256, 256>>>(x, xh, Wq, wqh, W1, w1h, W2, w2h);
    }

    // 1) K/V from rank-1 conditioner
    cond_kv_kernel<<<dim3(NC/128, NB), 128>>>(ce, Wk, bk, Wv, bv, convw, convb);

    // 2) q = x @ Wq^T + bq  (fp32 + fp16)
    gemm_h<0><<<dim3(NC/128, NBT/128, 1), 256, GEMM_SMEM>>>(
        xh, wqh, bq, q, qh, NC, NC, 1.0f, 0, 0, 0);

    // 3) fused attention + LN1 -> query (fp32 + fp16)
    attn_fused<<<dim3(NT/128, NB), 256, ATT_SMEM>>>(
        qh, kh, vTh, q, ln1w, ln1b, tmp, query, queryh);

    // 4) h = gelu(query @ W1^T + b1), fp16
    gemm_h<1><<<dim3(2*NC/128, NBT/128, 1), 256, GEMM_SMEM>>>(
        queryh, w1h, b1, nullptr, hh, NC, 2*NC, 1.0f, 0, 0, 0);

    // 5) ff = h @ W2^T + b2, fp32
    gemm_h<0><<<dim3(NC/128, NBT/128, 1), 256, GEMM_SMEM>>>(
        hh, w2h, b2, tmp, nullptr, 2*NC, NC, 1.0f, 0, 0, 0);

    // 6) out = LN2(query + ff) + x
    ln_kernel<<<NBT, 128>>>(query, tmp, ln2w, ln2b, x, out);
}

// round 10
// speedup vs baseline: 1.0894x; 1.0894x over previous
#include <cuda_runtime.h>
#include <cuda_fp16.h>
#include <math.h>
#include <cstdint>

// Problem dims (fixed)
#define NB 32
#define NT 1024
#define NC 512
#define NL 252
#define NP 256
#define NS 128
#define NBT (NB*NT)

// fp16 scratch only — all fp32 intermediates eliminated
static __device__ __half g_qh[NBT*NC];
static __device__ __half g_queryh[NBT*NC];
static __device__ __half g_uh[NBT*NC];
static __device__ __half g_tmph[NBT*NC];
static __device__ __half g_hh[NBT*2*NC];
static __device__ __half g_kh[NB*NS*NC];
static __device__ __half g_vTh[NB*NC*NS];
static __device__ __half g_wqh[NC*NC];
static __device__ __half g_w1h[2*NC*NC];
static __device__ __half g_w2h[NC*2*NC];

// ---------------------------------------------------------------------------
__device__ __forceinline__ uint32_t smem_u32(const void* p) {
    uint32_t a;
    asm("{ .reg .u64 t; cvta.to.shared.u64 t, %1; cvt.u32.u64 %0, t; }" : "=r"(a) : "l"(p));
    return a;
}
__device__ __forceinline__ void cp16(uint32_t dst, const void* src) {
    asm volatile("cp.async.cg.shared.global [%0], [%1], 16;" :: "r"(dst), "l"(src) : "memory");
}
template<int N> __device__ __forceinline__ void cp_wait() {
    asm volatile("cp.async.wait_group %0;" :: "n"(N) : "memory");
}
__device__ __forceinline__ void cp_commit() { asm volatile("cp.async.commit_group;" ::: "memory"); }

__device__ __forceinline__ void mma16(float* c, const uint32_t* a, uint32_t b0, uint32_t b1) {
    asm volatile(
        "mma.sync.aligned.m16n8k16.row.col.f32.f16.f16.f32 "
        "{%0,%1,%2,%3}, {%4,%5,%6,%7}, {%8,%9}, {%0,%1,%2,%3};"
        : "+f"(c[0]), "+f"(c[1]), "+f"(c[2]), "+f"(c[3])
        : "r"(a[0]), "r"(a[1]), "r"(a[2]), "r"(a[3]), "r"(b0), "r"(b1));
}
__device__ __forceinline__ void ldsm4(uint32_t* r, uint32_t addr) {
    asm volatile("ldmatrix.sync.aligned.m8n8.x4.shared.b16 {%0,%1,%2,%3}, [%4];"
                 : "=r"(r[0]), "=r"(r[1]), "=r"(r[2]), "=r"(r[3]) : "r"(addr));
}

// ---------------------------------------------------------------------------
// fp16 HMMA GEMM. AF32=1: A is fp32 in global, converted inline during staging.
// A: [M,K] K-major, B: [N,K] K-major half. CTA 128x128, BK=32, 256 thr.
// ---------------------------------------------------------------------------
#define SROWW 20
#define STG_WORDS (128*SROWW)
#define GEMM_SMEM (2*2*STG_WORDS*4)

template<int EPI, int AF32>
__global__ void __launch_bounds__(256)
gemm_h(const void* __restrict__ Ap, const __half* __restrict__ B,
       const float* __restrict__ bias, float* __restrict__ C, __half* __restrict__ Ch,
       int K, int ldc, float scale,
       long long sA, long long sB, long long sC)
{
    extern __shared__ uint32_t smw[];
    const uint32_t sbase = smem_u32(smw);
    const int tid = threadIdx.x;
    const int wid = tid >> 5, lane = tid & 31;
    const int g = lane >> 2, tig = lane & 3;
    const int wm = wid & 1, wn = wid >> 1;
    const int m0 = blockIdx.y * 128, n0 = blockIdx.x * 128;
    const float*  Af = (const float*)Ap  + (AF32 ? (blockIdx.z * sA + (long long)m0 * K) : 0);
    const __half* Ah = (const __half*)Ap + (AF32 ? 0 : (blockIdx.z * sA + (long long)m0 * K));
    B += blockIdx.z * sB + (long long)n0 * K;
    if (C)  C  += blockIdx.z * sC;
    if (Ch) Ch += blockIdx.z * sC;
    const int nk = K >> 5;
    const uint32_t lpart = (lane & 15) * 80 + ((lane >> 4) * 16);

    float acc[4][4][4];
#pragma unroll
    for (int i = 0; i < 4; i++)
#pragma unroll
        for (int j = 0; j < 4; j++)
#pragma unroll
            for (int q = 0; q < 4; q++) acc[i][j][q] = 0.f;

    float4 aregs[4];
    auto loadA = [&](int chunk) {      // AF32 path: fp32 A into registers
        const float* Ac = Af + chunk * 32;
#pragma unroll
        for (int i = 0; i < 4; i++) {
            int idx = i * 256 + tid;
            int row = idx >> 3, c4 = idx & 7;
            aregs[i] = *(const float4*)(Ac + (long long)row * K + c4 * 4);
        }
    };
    auto stsA = [&](int stg) {         // convert + store to smem
        uint32_t ab = sbase + stg * (2 * STG_WORDS * 4);
#pragma unroll
        for (int i = 0; i < 4; i++) {
            int idx = i * 256 + tid;
            int row = idx >> 3, c4 = idx & 7;
            __half2 h0 = __floats2half2_rn(aregs[i].x, aregs[i].y);
            __half2 h1 = __floats2half2_rn(aregs[i].z, aregs[i].w);
            asm volatile("st.shared.v2.u32 [%0], {%1,%2};"
                         :: "r"(ab + row * 80 + c4 * 8),
                            "r"(*(uint32_t*)&h0), "r"(*(uint32_t*)&h1));
        }
    };
    auto stageAB16 = [&](int chunk, int stg) {   // fp16 A + B via cp.async
        uint32_t ab = sbase + stg * (2 * STG_WORDS * 4);
        uint32_t bb = ab + STG_WORDS * 4;
        const __half* Ac = Ah + chunk * 32;
        const __half* Bc = B + chunk * 32;
#pragma unroll
        for (int i = 0; i < 2; i++) {
            int idx = i * 256 + tid;
            int row = idx >> 2, c8 = idx & 3;
            uint32_t so = row * 80 + c8 * 16;
            cp16(ab + so, Ac + (long long)row * K + c8 * 8);
            cp16(bb + so, Bc + (long long)row * K + c8 * 8);
        }
        cp_commit();
    };
    auto stageB = [&](int chunk, int stg) {      // B only (AF32 path)
        uint32_t bb = sbase + stg * (2 * STG_WORDS * 4) + STG_WORDS * 4;
        const __half* Bc = B + chunk * 32;
#pragma unroll
        for (int i = 0; i < 2; i++) {
            int idx = i * 256 + tid;
            int row = idx >> 2, c8 = idx & 3;
            cp16(bb + row * 80 + c8 * 16, Bc + (long long)row * K + c8 * 8);
        }
        cp_commit();
    };

    if (AF32) { stageB(0, 0); loadA(0); }
    else       stageAB16(0, 0);

    for (int kc = 0; kc < nk; kc++) {
        if (AF32) {
            stsA(kc & 1);
            if (kc + 1 < nk) { stageB(kc + 1, (kc + 1) & 1); loadA(kc + 1); cp_wait<1>(); }
            else             { cp_wait<0>(); }
        } else {
            if (kc + 1 < nk) { stageAB16(kc + 1, (kc + 1) & 1); cp_wait<1>(); }
            else             { cp_wait<0>(); }
        }
        __syncthreads();
        const uint32_t base = sbase + (kc & 1) * (2 * STG_WORDS * 4);
        const uint32_t Abase = base + (wm * 64) * 80 + lpart;
        const uint32_t Bbase = base + STG_WORDS * 4 + (wn * 32) * 80 + lpart;
#pragma unroll
        for (int slab = 0; slab < 2; slab++) {
            uint32_t af[4][4], bf[2][4];
#pragma unroll
            for (int mt = 0; mt < 4; mt++)
                ldsm4(af[mt], Abase + mt * (16 * 80) + slab * 32);
#pragma unroll
            for (int np = 0; np < 2; np++)
                ldsm4(bf[np], Bbase + np * (16 * 80) + slab * 32);
#pragma unroll
            for (int mt = 0; mt < 4; mt++)
#pragma unroll
                for (int np = 0; np < 2; np++) {
                    mma16(acc[mt][np * 2 + 0], af[mt], bf[np][0], bf[np][2]);
                    mma16(acc[mt][np * 2 + 1], af[mt], bf[np][1], bf[np][3]);
                }
        }
        __syncthreads();
    }

#pragma unroll
    for (int mt = 0; mt < 4; mt++) {
#pragma unroll
        for (int hf = 0; hf < 2; hf++) {
            int row = m0 + wm * 64 + mt * 16 + g + hf * 8;
#pragma unroll
            for (int nt = 0; nt < 4; nt++) {
                int col = n0 + wn * 32 + nt * 8 + 2 * tig;
                float v0 = acc[mt][nt][hf * 2 + 0] * scale;
                float v1 = acc[mt][nt][hf * 2 + 1] * scale;
                if (bias) { v0 += bias[col]; v1 += bias[col + 1]; }
                if (EPI == 1) {
                    v0 = 0.5f * v0 * (1.0f + erff(v0 * 0.70710678118654752f));
                    v1 = 0.5f * v1 * (1.0f + erff(v1 * 0.70710678118654752f));
                }
                if (C) {
                    float2 o; o.x = v0; o.y = v1;
                    *(float2*)(C + (long long)row * ldc + col) = o;
                }
                if (Ch)
                    *(__half2*)(Ch + (long long)row * ldc + col) = __floats2half2_rn(v0, v1);
            }
        }
    }
}

// ---------------------------------------------------------------------------
// Fused attention: scores = qh@kh^T, softmax, P@V, + qh residual, LN1.
// All global I/O fp16. LN stats computed from fp32 registers.
// ---------------------------------------------------------------------------
#define ATT_SMEM 93184
#define PROWW 68

__global__ void __launch_bounds__(256)
attn_fused(const __half* __restrict__ qhp, const __half* __restrict__ khp,
           const __half* __restrict__ vTp,
           const float* __restrict__ lnw, const float* __restrict__ lnb,
           __half* __restrict__ uh, __half* __restrict__ queryh)
{
    extern __shared__ uint32_t smw[];
    const uint32_t sbase = smem_u32(smw);
    const int tid = threadIdx.x;
    const int wid = tid >> 5, lane = tid & 31;
    const int g = lane >> 2, tig = lane & 3;
    const int wm = wid & 1, wn = wid >> 1;
    const int m0 = blockIdx.x * 128;
    const int b = blockIdx.y;
    const __half* A = qhp + ((long long)b * NT + m0) * NC;
    const __half* B = khp + (long long)b * NS * NC;
    const __half* V = vTp + (long long)b * NC * NS;
    const int slot = wn * 4 + tig;
    const uint32_t lp80  = (lane & 15) * 80  + ((lane >> 4) * 16);
    const uint32_t lp272 = (lane & 15) * 272 + ((lane >> 4) * 16);

    float* RED = (float*)(smw + 18944);
    float* RSQ = RED + 2048;
    float2* RST = (float2*)(smw + 23040);

    float acc[4][4][4];
#pragma unroll
    for (int i = 0; i < 4; i++)
#pragma unroll
        for (int j = 0; j < 4; j++)
#pragma unroll
            for (int q = 0; q < 4; q++) acc[i][j][q] = 0.f;

    // ---- Phase 1: scores = Q K^T ----
    auto stage = [&](int chunk, int stg) {
        uint32_t ab = sbase + stg * (2 * STG_WORDS * 4);
        uint32_t bb = ab + STG_WORDS * 4;
        const __half* Ac = A + chunk * 32;
        const __half* Bc = B + chunk * 32;
#pragma unroll
        for (int i = 0; i < 2; i++) {
            int idx = i * 256 + tid;
            int row = idx >> 2, c8 = idx & 3;
            uint32_t so = row * 80 + c8 * 16;
            cp16(ab + so, Ac + (long long)row * NC + c8 * 8);
            cp16(bb + so, Bc + (long long)row * NC + c8 * 8);
        }
        cp_commit();
    };

    stage(0, 0);
    for (int kc = 0; kc < 16; kc++) {
        if (kc + 1 < 16) { stage(kc + 1, (kc + 1) & 1); cp_wait<1>(); }
        else            { cp_wait<0>(); }
        __syncthreads();
        const uint32_t base = sbase + (kc & 1) * (2 * STG_WORDS * 4);
        const uint32_t Abase = base + (wm * 64) * 80 + lp80;
        const uint32_t Bbase = base + STG_WORDS * 4 + (wn * 32) * 80 + lp80;
#pragma unroll
        for (int slab = 0; slab < 2; slab++) {
            uint32_t af[4][4], bf[2][4];
#pragma unroll
            for (int mt = 0; mt < 4; mt++)
                ldsm4(af[mt], Abase + mt * (16 * 80) + slab * 32);
#pragma unroll
            for (int np = 0; np < 2; np++)
                ldsm4(bf[np], Bbase + np * (16 * 80) + slab * 32);
#pragma unroll
            for (int mt = 0; mt < 4; mt++)
#pragma unroll
                for (int np = 0; np < 2; np++) {
                    mma16(acc[mt][np * 2 + 0], af[mt], bf[np][0], bf[np][2]);
                    mma16(acc[mt][np * 2 + 1], af[mt], bf[np][1], bf[np][3]);
                }
        }
        __syncthreads();
    }

    // ---- Phase 2: softmax ----
    const float scl = 0.04419417382415922f;  // 1/sqrt(512)
#pragma unroll
    for (int idx = 0; idx < 8; idx++) {
        int mt = idx >> 1, hf = idx & 1;
        float m = -1e30f;
#pragma unroll
        for (int nt = 0; nt < 4; nt++) {
            m = fmaxf(m, acc[mt][nt][hf * 2 + 0]);
            m = fmaxf(m, acc[mt][nt][hf * 2 + 1]);
        }
        int r = wm * 64 + mt * 16 + g + hf * 8;
        RED[r * 16 + slot] = m;
    }
    __syncthreads();
    if (tid < 128) {
        float m = -1e30f;
#pragma unroll
        for (int k = 0; k < 16; k++) m = fmaxf(m, RED[tid * 16 + k]);
        RST[tid].x = m;
    }
    __syncthreads();
#pragma unroll
    for (int idx = 0; idx < 8; idx++) {
        int mt = idx >> 1, hf = idx & 1;
        int r = wm * 64 + mt * 16 + g + hf * 8;
        float rmax = RST[r].x;
        float s = 0.f;
#pragma unroll
        for (int nt = 0; nt < 4; nt++) {
            float p0 = expf(scl * (acc[mt][nt][hf * 2 + 0] - rmax));
            float p1 = expf(scl * (acc[mt][nt][hf * 2 + 1] - rmax));
            acc[mt][nt][hf * 2 + 0] = p0;
            acc[mt][nt][hf * 2 + 1] = p1;
            s += p0 + p1;
        }
        RED[r * 16 + slot] = s;
    }
    __syncthreads();
    if (tid < 128) {
        float s = 0.f;
#pragma unroll
        for (int k = 0; k < 16; k++) s += RED[tid * 16 + k];
        RST[tid].y = 1.0f / s;
    }
    __syncthreads();
#pragma unroll
    for (int idx = 0; idx < 8; idx++) {
        int mt = idx >> 1, hf = idx & 1;
        int r = wm * 64 + mt * 16 + g + hf * 8;
        float inv = RST[r].y;
#pragma unroll
        for (int nt = 0; nt < 4; nt++) {
            __half2 h = __floats2half2_rn(acc[mt][nt][hf * 2 + 0] * inv,
                                          acc[mt][nt][hf * 2 + 1] * inv);
            smw[10240 + r * PROWW + wn * 16 + nt * 4 + tig] = *(uint32_t*)&h;
        }
    }
    __syncthreads();

    // ---- Phase 3: P @ V, + qh residual, LN1 stats ----
    float psum[8], psq[8];
#pragma unroll
    for (int i = 0; i < 8; i++) { psum[i] = 0.f; psq[i] = 0.f; }
    const uint32_t Pbase = sbase + 40960 + (wm * 64) * 272 + lp272;

    for (int chunk = 0; chunk < 4; chunk++) {
#pragma unroll
        for (int i = 0; i < 8; i++) {
            int idx = i * 256 + tid;
            int row = idx >> 4, c16 = idx & 15;
            cp16(sbase + row * 272 + c16 * 16,
                 V + (long long)(chunk * 128 + row) * NS + c16 * 8);
        }
        cp_commit(); cp_wait<0>();
        __syncthreads();

        float a2[4][4][4];
#pragma unroll
        for (int i = 0; i < 4; i++)
#pragma unroll
            for (int j = 0; j < 4; j++)
#pragma unroll
                for (int q = 0; q < 4; q++) a2[i][j][q] = 0.f;

        const uint32_t Vbase = sbase + (wn * 32) * 272 + lp272;
#pragma unroll
        for (int slab = 0; slab < 8; slab++) {
            uint32_t af[4][4], bf[2][4];
#pragma unroll
            for (int mt = 0; mt < 4; mt++)
                ldsm4(af[mt], Pbase + mt * (16 * 272) + slab * 32);
#pragma unroll
            for (int np = 0; np < 2; np++)
                ldsm4(bf[np], Vbase + np * (16 * 272) + slab * 32);
#pragma unroll
            for (int mt = 0; mt < 4; mt++)
#pragma unroll
                for (int np = 0; np < 2; np++) {
                    mma16(a2[mt][np * 2 + 0], af[mt], bf[np][0], bf[np][2]);
                    mma16(a2[mt][np * 2 + 1], af[mt], bf[np][1], bf[np][3]);
                }
        }

#pragma unroll
        for (int idx = 0; idx < 8; idx++) {
            int mt = idx >> 1, hf = idx & 1;
            long long grow = (long long)b * NT + m0 + wm * 64 + mt * 16 + g + hf * 8;
#pragma unroll
            for (int nt = 0; nt < 4; nt++) {
                int col = chunk * 128 + wn * 32 + nt * 8 + 2 * tig;
                __half2 qv2 = *(const __half2*)(qhp + grow * NC + col);
                float2 qv = __half22float2(qv2);
                float u0 = a2[mt][nt][hf * 2 + 0] + qv.x;
                float u1 = a2[mt][nt][hf * 2 + 1] + qv.y;
                psum[idx] += u0 + u1;
                psq[idx]  += u0 * u0 + u1 * u1;
                *(__half2*)(uh + grow * NC + col) = __floats2half2_rn(u0, u1);
            }
        }
        __syncthreads();
    }

    // ---- LN1 reduce + normalize ----
#pragma unroll
    for (int idx = 0; idx < 8; idx++) {
        int mt = idx >> 1, hf = idx & 1;
        int r = wm * 64 + mt * 16 + g + hf * 8;
        RED[r * 16 + slot] = psum[idx];
        RSQ[r * 16 + slot] = psq[idx];
    }
    __syncthreads();
    if (tid < 128) {
        float s = 0.f, sq = 0.f;
#pragma unroll
        for (int k = 0; k < 16; k++) { s += RED[tid * 16 + k]; sq += RSQ[tid * 16 + k]; }
        float mu = s * (1.0f / NC);
        float var = sq * (1.0f / NC) - mu * mu;
        RST[tid].x = mu;
        RST[tid].y = rsqrtf(var + 1e-5f);
    }
    __syncthreads();
#pragma unroll
    for (int idx = 0; idx < 8; idx++) {
        int mt = idx >> 1, hf = idx & 1;
        int r = wm * 64 + mt * 16 + g + hf * 8;
        float2 st = RST[r];
        long long grow = (long long)b * NT + m0 + r;
#pragma unroll
        for (int chunk = 0; chunk < 4; chunk++) {
#pragma unroll
            for (int nt = 0; nt < 4; nt++) {
                int col = chunk * 128 + wn * 32 + nt * 8 + 2 * tig;
                float2 u = __half22float2(*(const __half2*)(uh + grow * NC + col));
                float o0 = (u.x - st.x) * st.y * lnw[col]     + lnb[col];
                float o1 = (u.y - st.x) * st.y * lnw[col + 1] + lnb[col + 1];
                *(__half2*)(queryh + grow * NC + col) = __floats2half2_rn(o0, o1);
            }
        }
    }
}

// ---------------------------------------------------------------------------
// K/V via rank-1 conditioner (fp16 outputs)
// ---------------------------------------------------------------------------
__global__ void cond_kv_kernel(const float* __restrict__ cond_emb,
                               const float* __restrict__ Wk, const float* __restrict__ bk,
                               const float* __restrict__ Wv, const float* __restrict__ bv,
                               const float* __restrict__ conv_w, const float* __restrict__ conv_b)
{
    int b = blockIdx.y;
    int c = blockIdx.x * blockDim.x + threadIdx.x;
    __shared__ float pad[NP];
    const float* ce = cond_emb + (long long)b * NL;
    for (int j = threadIdx.x; j < NP; j += blockDim.x)
        pad[j] = ce[(j + NL - 2) % NL];
    __syncthreads();

    float pk = 0.f, pv = 0.f, wks = 0.f, wvs = 0.f;
    const float* wkr = Wk + (long long)c * NP;
    const float* wvr = Wv + (long long)c * NP;
#pragma unroll 4
    for (int j = 0; j < NP; j++) {
        float p = pad[j];
        float a = wkr[j], bb = wvr[j];
        pk += p * a;  wks += a;
        pv += p * bb; wvs += bb;
    }
    float bkc = bk[c], bvc = bv[c];
    for (int s = 0; s < NS; s++) {
        float cw = conv_w[s], cb = conv_b[s];
        g_kh[((long long)b * NS + s) * NC + c]  = __float2half_rn(cw * pk + cb * wks + bkc);
        g_vTh[((long long)b * NC + c) * NS + s] = __float2half_rn(cw * pv + cb * wvs + bvc);
    }
}

// ---------------------------------------------------------------------------
// Weight conversions only (x converted inline in q-GEMM)
// ---------------------------------------------------------------------------
__global__ void cvt_w_kernel(const float* __restrict__ Wq, __half* __restrict__ wqh,
                             const float* __restrict__ W1, __half* __restrict__ w1h,
                             const float* __restrict__ W2, __half* __restrict__ w2h)
{
    const int n0 = NC*NC/4, n1 = n0 + 2*NC*NC/4, n2 = n1 + 2*NC*NC/4;
    int i = blockIdx.x * blockDim.x + threadIdx.x;
    const float* s; __half* d; int off;
    if      (i < n0) { s = Wq; d = wqh; off = i; }
    else if (i < n1) { s = W1; d = w1h; off = i - n0; }
    else if (i < n2) { s = W2; d = w2h; off = i - n1; }
    else return;
    float4 v = ((const float4*)s)[off];
    ((__half2*)d)[2*off]   = __floats2half2_rn(v.x, v.y);
    ((__half2*)d)[2*off+1] = __floats2half2_rn(v.z, v.w);
}

// ---------------------------------------------------------------------------
// Final: out = LN(ah + bh)*w + bb + x   (ah, bh fp16; math fp32)
// ---------------------------------------------------------------------------
__global__ void ln_kernel(const __half* __restrict__ ah, const __half* __restrict__ bh,
                          const float* __restrict__ w, const float* __restrict__ bb,
                          const float* __restrict__ x, float* __restrict__ out)
{
    long long row = blockIdx.x;
    int t = threadIdx.x;
    float2 a0 = __half22float2(((const __half2*)(ah + row * NC))[t * 2]);
    float2 a1 = __half22float2(((const __half2*)(ah + row * NC))[t * 2 + 1]);
    float2 b0 = __half22float2(((const __half2*)(bh + row * NC))[t * 2]);
    float2 b1 = __half22float2(((const __half2*)(bh + row * NC))[t * 2 + 1]);
    float4 u; u.x = a0.x + b0.x; u.y = a0.y + b0.y; u.z = a1.x + b1.x; u.w = a1.y + b1.y;
    float s  = u.x + u.y + u.z + u.w;
    float sq = u.x*u.x + u.y*u.y + u.z*u.z + u.w*u.w;
#pragma unroll
    for (int o = 16; o; o >>= 1) {
        s  += __shfl_xor_sync(0xffffffffu, s,  o);
        sq += __shfl_xor_sync(0xffffffffu, sq, o);
    }
    __shared__ float ss[4], sqs[4];
    int wid = t >> 5, lane = t & 31;
    if (lane == 0) { ss[wid] = s; sqs[wid] = sq; }
    __syncthreads();
    s  = ss[0] + ss[1] + ss[2] + ss[3];
    sq = sqs[0] + sqs[1] + sqs[2] + sqs[3];
    float mu  = s * (1.0f / NC);
    float var = sq * (1.0f / NC) - mu * mu;
    float inv = rsqrtf(var + 1e-5f);
    float4 wv  = ((const float4*)w)[t];
    float4 bv2 = ((const float4*)bb)[t];
    float4 xv  = ((const float4*)(x + row * NC))[t];
    float4 o;
    o.x = (u.x - mu) * inv * wv.x + bv2.x + xv.x;
    o.y = (u.y - mu) * inv * wv.y + bv2.y + xv.y;
    o.z = (u.z - mu) * inv * wv.z + bv2.z + xv.z;
    o.w = (u.w - mu) * inv * wv.w + bv2.w + xv.w;
    ((float4*)(out + row * NC))[t] = o;
}

// ---------------------------------------------------------------------------
extern "C" void kernel_launch(void* const* d_in, const int* in_sizes, int n_in,
                              void* d_out, int out_size)
{
    const float* x     = (const float*)d_in[0];
    const float* ce    = (const float*)d_in[1];
    const float* Wq    = (const float*)d_in[2];
    const float* bq    = (const float*)d_in[3];
    const float* Wk    = (const float*)d_in[4];
    const float* bk    = (const float*)d_in[5];
    const float* Wv    = (const float*)d_in[6];
    const float* bv    = (const float*)d_in[7];
    const float* convw = (const float*)d_in[8];
    const float* convb = (const float*)d_in[9];
    const float* ln1w  = (const float*)d_in[10];
    const float* ln1b  = (const float*)d_in[11];
    const float* W1    = (const float*)d_in[12];
    const float* b1    = (const float*)d_in[13];
    const float* W2    = (const float*)d_in[14];
    const float* b2    = (const float*)d_in[15];
    const float* ln2w  = (const float*)d_in[16];
    const float* ln2b  = (const float*)d_in[17];
    float* out = (float*)d_out;

    __half *qh, *queryh, *uh, *tmph, *hh, *kh, *vTh, *wqh, *w1h, *w2h;
    cudaGetSymbolAddress((void**)&qh,     g_qh);
    cudaGetSymbolAddress((void**)&queryh, g_queryh);
    cudaGetSymbolAddress((void**)&uh,     g_uh);
    cudaGetSymbolAddress((void**)&tmph,   g_tmph);
    cudaGetSymbolAddress((void**)&hh,     g_hh);
    cudaGetSymbolAddress((void**)&kh,     g_kh);
    cudaGetSymbolAddress((void**)&vTh,    g_vTh);
    cudaGetSymbolAddress((void**)&wqh,    g_wqh);
    cudaGetSymbolAddress((void**)&w1h,    g_w1h);
    cudaGetSymbolAddress((void**)&w2h,    g_w2h);

    cudaFuncSetAttribute(gemm_h<0,0>, cudaFuncAttributeMaxDynamicSharedMemorySize, GEMM_SMEM);
    cudaFuncSetAttribute(gemm_h<1,0>, cudaFuncAttributeMaxDynamicSharedMemorySize, GEMM_SMEM);
    cudaFuncSetAttribute(gemm_h<0,1>, cudaFuncAttributeMaxDynamicSharedMemorySize, GEMM_SMEM);
    cudaFuncSetAttribute(attn_fused, cudaFuncAttributeMaxDynamicSharedMemorySize, ATT_SMEM);

    // 0) convert weights to fp16
    {
        int n = (NC*NC + 2*NC*NC + 2*NC*NC) / 4;
        cvt_w_kernel<<<(n + 255)/256, 256>>>(Wq, wqh, W1, w1h, W2, w2h);
    }

    // 1) K/V from rank-1 conditioner
    cond_kv_kernel<<<dim3(NC/128, NB), 128>>>(ce, Wk, bk, Wv, bv, convw, convb);

    // 2) qh = fp16(x @ Wq^T + bq)   (x fp32 converted inline)
    gemm_h<0,1><<<dim3(NC/128, NBT/128, 1), 256, GEMM_SMEM>>>(
        x, wqh, bq, nullptr, qh, NC, NC, 1.0f, 0, 0, 0);

    // 3) fused attention + LN1 -> queryh
    attn_fused<<<dim3(NT/128, NB), 256, ATT_SMEM>>>(
        qh, kh, vTh, ln1w, ln1b, uh, queryh);

    // 4) hh = fp16(gelu(query @ W1^T + b1))
    gemm_h<1,0><<<dim3(2*NC/128, NBT/128, 1), 256, GEMM_SMEM>>>(
        queryh, w1h, b1, nullptr, hh, NC, 2*NC, 1.0f, 0, 0, 0);

    // 5) tmph = fp16(h @ W2^T + b2)
    gemm_h<0,0><<<dim3(NC/128, NBT/128, 1), 256, GEMM_SMEM>>>(
        hh, w2h, b2, nullptr, tmph, 2*NC, NC, 1.0f, 0, 0, 0);

    // 6) out = LN2(query + ff) + x
    ln_kernel<<<NBT, 128>>>(queryh, tmph, ln2w, ln2b, x, out);
}